// round 10
// baseline (speedup 1.0000x reference)
#include <cuda_runtime.h>
#include <cuda_fp16.h>

#define BB    32
#define TT    12
#define NNODE 5000
#define CCH   8
#define EEDGE 5000
#define MEDGE 160000
#define LAMW  0.3f
#define EPSW  1e-8f
#define NCHUNK 5              // finalize blocks per b
#define FEAT_BLOCKS 1036      // 148 SMs x 7 resident blocks -> exactly one wave

// normalized features in fp16. Record per node = 1024B = 64 uint4.
// uint4 index within record: (b>>4)*32 + (b&15)*2 + half,
// half 0 = [mean(c0..3), std(c0..3)], half 1 = [mean(c4..7), std(c4..7)]
// (permuted vs reference order — dot product is permutation-invariant).
__device__ uint4 g_fhat[(size_t)NNODE * 64];
// segment accumulators, layout (b, e)
__device__ float g_acc[(size_t)BB * EEDGE];
// reciprocal counts
__device__ float g_icnt[EEDGE];

// ---------------------------------------------------------------------------
// Kernel 1: feat, split by channel-half, PERSISTENT one-wave grid-stride.
// 2*B*N = 320000 items over 265216 threads: each thread does 1-2 items,
// spread evenly over all SMs (no whole-block tail wave).
// Folded: zero-acc + icnt init.
// ---------------------------------------------------------------------------
__global__ void feat_kernel(const float* __restrict__ x,
                            const float* __restrict__ counts) {
    const int STRIDE4 = (NNODE * CCH) / 4;          // float4s per t-step
    const int nthreads = gridDim.x * blockDim.x;

    for (int tid = blockIdx.x * blockDim.x + threadIdx.x;
         tid < 2 * BB * NNODE; tid += nthreads) {

        if (tid < (BB * EEDGE) / 4)
            reinterpret_cast<float4*>(g_acc)[tid] = make_float4(0.f, 0.f, 0.f, 0.f);
        if (tid < EEDGE)
            g_icnt[tid] = 1.0f / fmaxf(counts[tid], 1.f);

        int half = tid & 1;
        int nb   = tid >> 1;
        int n    = nb % NNODE;
        int b    = nb / NNODE;

        const float4* src = reinterpret_cast<const float4*>(
            x + (((size_t)b * TT) * NNODE + n) * CCH) + half;

        float4 s  = make_float4(0.f, 0.f, 0.f, 0.f);
        float4 sq = make_float4(0.f, 0.f, 0.f, 0.f);

#pragma unroll
        for (int t = 0; t < TT; t++) {
            float4 a = __ldcs(src + (size_t)t * STRIDE4);   // streaming
            s.x += a.x; s.y += a.y; s.z += a.z; s.w += a.w;
            sq.x = fmaf(a.x, a.x, sq.x);
            sq.y = fmaf(a.y, a.y, sq.y);
            sq.z = fmaf(a.z, a.z, sq.z);
            sq.w = fmaf(a.w, a.w, sq.w);
        }

        float f[8];
        {
            float sv[4]  = {s.x, s.y, s.z, s.w};
            float sqv[4] = {sq.x, sq.y, sq.z, sq.w};
#pragma unroll
            for (int k = 0; k < 4; k++) {
                float m   = sv[k] * (1.0f / TT);
                float var = (sqv[k] - (float)TT * m * m) * (1.0f / (TT - 1));
                float sd  = sqrtf(fmaxf(var, 0.f));
                f[k]     = m;
                f[4 + k] = sd;
            }
        }
        float nrm2 = 0.f;
#pragma unroll
        for (int k = 0; k < 8; k++) nrm2 = fmaf(f[k], f[k], nrm2);
        // pair lane holds the other channel-half of the same (b, n):
        // stride is a multiple of 32, so tid parity == lane parity always.
        nrm2 += __shfl_xor_sync(0xffffffffu, nrm2, 1);
        float inv = 1.0f / fmaxf(sqrtf(nrm2), EPSW);

        union { __half2 h2[4]; uint4 u4; } pk;
#pragma unroll
        for (int k = 0; k < 4; k++)
            pk.h2[k] = __floats2half2_rn(f[2 * k] * inv, f[2 * k + 1] * inv);

        g_fhat[(size_t)n * 64 + (b >> 4) * 32 + (b & 15) * 2 + half] = pk.u4;
    }
}

// ---------------------------------------------------------------------------
// Kernel 2: sim (unchanged)
// ---------------------------------------------------------------------------
__global__ void sim_kernel(const int* __restrict__ members,
                           const int* __restrict__ eids) {
    int warp = (blockIdx.x * blockDim.x + threadIdx.x) >> 5;
    int lane = threadIdx.x & 31;
    int m0 = warp * 32;
    if (m0 >= MEDGE) return;

    int my_b = ((lane & 1) << 4) | (lane >> 1);

    int my_node = members[m0 + lane];
    int my_e    = eids[m0 + lane];

    float vf0[8], vf1[8];
    int   cur_e = -1;
    float acc   = 0.f;

    for (int i = 0; i < 32; i++) {
        int node = __shfl_sync(0xffffffffu, my_node, i);
        int e    = __shfl_sync(0xffffffffu, my_e, i);

        if (e != cur_e) {
            if (cur_e >= 0)
                atomicAdd(&g_acc[(size_t)my_b * EEDGE + cur_e], acc);
            acc = 0.f;
            const uint4* pv = g_fhat + (size_t)e * 64;
            union { uint4 u; __half2 h[4]; } a0, a1;
            a0.u = pv[lane];
            a1.u = pv[32 + lane];
#pragma unroll
            for (int k = 0; k < 4; k++) {
                float2 t0 = __half22float2(a0.h[k]);
                float2 t1 = __half22float2(a1.h[k]);
                vf0[2 * k] = t0.x; vf0[2 * k + 1] = t0.y;
                vf1[2 * k] = t1.x; vf1[2 * k + 1] = t1.y;
            }
            cur_e = e;
        }

        const uint4* pu = g_fhat + (size_t)node * 64;
        union { uint4 u; __half2 h[4]; } b0, b1;
        b0.u = pu[lane];
        b1.u = pu[32 + lane];

        float d0, d1;
        {
            float2 t = __half22float2(b0.h[0]);
            d0 = t.x * vf0[0]; d0 = fmaf(t.y, vf0[1], d0);
            t = __half22float2(b0.h[1]);
            d0 = fmaf(t.x, vf0[2], d0); d0 = fmaf(t.y, vf0[3], d0);
            t = __half22float2(b0.h[2]);
            d0 = fmaf(t.x, vf0[4], d0); d0 = fmaf(t.y, vf0[5], d0);
            t = __half22float2(b0.h[3]);
            d0 = fmaf(t.x, vf0[6], d0); d0 = fmaf(t.y, vf0[7], d0);

            t = __half22float2(b1.h[0]);
            d1 = t.x * vf1[0]; d1 = fmaf(t.y, vf1[1], d1);
            t = __half22float2(b1.h[1]);
            d1 = fmaf(t.x, vf1[2], d1); d1 = fmaf(t.y, vf1[3], d1);
            t = __half22float2(b1.h[2]);
            d1 = fmaf(t.x, vf1[4], d1); d1 = fmaf(t.y, vf1[5], d1);
            t = __half22float2(b1.h[3]);
            d1 = fmaf(t.x, vf1[6], d1); d1 = fmaf(t.y, vf1[7], d1);
        }

        d0 += __shfl_xor_sync(0xffffffffu, d0, 1);
        d1 += __shfl_xor_sync(0xffffffffu, d1, 1);

        float d = (lane & 1) ? d1 : d0;
        acc += fminf(fmaxf(d, 0.f), 1.f);
    }
    atomicAdd(&g_acc[(size_t)my_b * EEDGE + cur_e], acc);
}

// ---------------------------------------------------------------------------
// Kernel 3: fused finalize (unchanged). Grid (NCHUNK, BB), block 256.
// ---------------------------------------------------------------------------
__global__ void finalize_kernel(const float* __restrict__ W,
                                float* __restrict__ out) {
    int b = blockIdx.y;
    const float4* arow = reinterpret_cast<const float4*>(g_acc + (size_t)b * EEDGE);
    const float4* crow = reinterpret_cast<const float4*>(g_icnt);
    const int NV4 = EEDGE / 4;                        // 1250

    float mn = 1e30f, mx = 0.f;                       // values >= 0
#pragma unroll
    for (int k = 0; k < NCHUNK; k++) {
        int i4 = k * 256 + threadIdx.x;
        if (i4 < NV4) {
            float4 a = arow[i4];
            float4 c = crow[i4];
            float s0 = a.x * c.x, s1 = a.y * c.y, s2 = a.z * c.z, s3 = a.w * c.w;
            mn = fminf(mn, fminf(fminf(s0, s1), fminf(s2, s3)));
            mx = fmaxf(mx, fmaxf(fmaxf(s0, s1), fmaxf(s2, s3)));
        }
    }
#pragma unroll
    for (int o = 16; o; o >>= 1) {
        mn = fminf(mn, __shfl_xor_sync(0xffffffffu, mn, o));
        mx = fmaxf(mx, __shfl_xor_sync(0xffffffffu, mx, o));
    }
    __shared__ float smn[8], smx[8];
    int wid = threadIdx.x >> 5, lane = threadIdx.x & 31;
    if (lane == 0) { smn[wid] = mn; smx[wid] = mx; }
    __syncthreads();
    mn = smn[0]; mx = smx[0];
#pragma unroll
    for (int i = 1; i < 8; i++) {
        mn = fminf(mn, smn[i]);
        mx = fmaxf(mx, smx[i]);
    }
    float inv = LAMW / (mx - mn + EPSW);

    int i4 = blockIdx.x * 256 + threadIdx.x;
    if (i4 < NV4) {
        float4 a = arow[i4];
        float4 c = crow[i4];
        float4 w = reinterpret_cast<const float4*>(W)[i4];
        float4 o;
        o.x = w.x * (1.f + (a.x * c.x - mn) * inv);
        o.y = w.y * (1.f + (a.y * c.y - mn) * inv);
        o.z = w.z * (1.f + (a.z * c.z - mn) * inv);
        o.w = w.w * (1.f + (a.w * c.w - mn) * inv);
        reinterpret_cast<float4*>(out + (size_t)b * EEDGE)[i4] = o;
    }
}

// ---------------------------------------------------------------------------
extern "C" void kernel_launch(void* const* d_in, const int* in_sizes, int n_in,
                              void* d_out, int out_size) {
    const float* x_raw   = (const float*)d_in[0];
    const float* W       = (const float*)d_in[1];
    const int*   members = (const int*)d_in[2];
    // d_in[3] = centers (== arange(E), unused)
    const int*   eids    = (const int*)d_in[4];
    const float* counts  = (const float*)d_in[5];
    float*       out     = (float*)d_out;

    feat_kernel<<<FEAT_BLOCKS, 256>>>(x_raw, counts);

    int warps  = (MEDGE + 31) / 32;                 // 5000
    int blocks = (warps * 32 + 255) / 256;          // 625
    sim_kernel<<<blocks, 256>>>(members, eids);

    dim3 fin_grid(NCHUNK, BB);
    finalize_kernel<<<fin_grid, 256>>>(W, out);
}

// round 11
// speedup vs baseline: 1.1658x; 1.1658x over previous
#include <cuda_runtime.h>
#include <cuda_fp16.h>

#define BB    32
#define TT    12
#define NNODE 5000
#define CCH   8
#define EEDGE 5000
#define MEDGE 160000
#define LAMW  0.3f
#define EPSW  1e-8f
#define NCHUNK 5              // finalize blocks per b

// normalized features in fp16. Record per node = 1024B = 64 uint4.
// uint4 index within record: (b>>4)*32 + (b&15)*2 + half,
// half 0 = [mean(c0..3), std(c0..3)], half 1 = [mean(c4..7), std(c4..7)]
// (permuted vs reference order — dot product is permutation-invariant).
__device__ uint4 g_fhat[(size_t)NNODE * 64];
// segment accumulators, layout (b, e)
__device__ float g_acc[(size_t)BB * EEDGE];
// reciprocal counts
__device__ float g_icnt[EEDGE];

// ---------------------------------------------------------------------------
// Kernel 1: feat (R9 config — best measured). Split by channel-half,
// 2*B*N threads, 12x16B streaming loads each. Folded zero-acc + icnt.
// ---------------------------------------------------------------------------
__global__ void feat_kernel(const float* __restrict__ x,
                            const float* __restrict__ counts) {
    int tid = blockIdx.x * blockDim.x + threadIdx.x;
    if (tid < (BB * EEDGE) / 4)
        reinterpret_cast<float4*>(g_acc)[tid] = make_float4(0.f, 0.f, 0.f, 0.f);
    if (tid < EEDGE)
        g_icnt[tid] = 1.0f / fmaxf(counts[tid], 1.f);
    if (tid >= 2 * BB * NNODE) return;

    int half = tid & 1;
    int nb   = tid >> 1;
    int n    = nb % NNODE;
    int b    = nb / NNODE;

    const float4* src = reinterpret_cast<const float4*>(
        x + (((size_t)b * TT) * NNODE + n) * CCH) + half;
    const int STRIDE4 = (NNODE * CCH) / 4;          // float4s per t-step

    float4 s  = make_float4(0.f, 0.f, 0.f, 0.f);
    float4 sq = make_float4(0.f, 0.f, 0.f, 0.f);

#pragma unroll
    for (int t = 0; t < TT; t++) {
        float4 a = __ldcs(src + (size_t)t * STRIDE4);   // streaming, single-use
        s.x += a.x; s.y += a.y; s.z += a.z; s.w += a.w;
        sq.x = fmaf(a.x, a.x, sq.x);
        sq.y = fmaf(a.y, a.y, sq.y);
        sq.z = fmaf(a.z, a.z, sq.z);
        sq.w = fmaf(a.w, a.w, sq.w);
    }

    float f[8];
    {
        float sv[4]  = {s.x, s.y, s.z, s.w};
        float sqv[4] = {sq.x, sq.y, sq.z, sq.w};
#pragma unroll
        for (int k = 0; k < 4; k++) {
            float m   = sv[k] * (1.0f / TT);
            float var = (sqv[k] - (float)TT * m * m) * (1.0f / (TT - 1));
            float sd  = sqrtf(fmaxf(var, 0.f));
            f[k]     = m;
            f[4 + k] = sd;
        }
    }
    float nrm2 = 0.f;
#pragma unroll
    for (int k = 0; k < 8; k++) nrm2 = fmaf(f[k], f[k], nrm2);
    // pair lane holds the other channel-half of the same (b, n)
    nrm2 += __shfl_xor_sync(0xffffffffu, nrm2, 1);
    float inv = 1.0f / fmaxf(sqrtf(nrm2), EPSW);

    union { __half2 h2[4]; uint4 u4; } pk;
#pragma unroll
    for (int k = 0; k < 4; k++)
        pk.h2[k] = __floats2half2_rn(f[2 * k] * inv, f[2 * k + 1] * inv);

    g_fhat[(size_t)n * 64 + (b >> 4) * 32 + (b & 15) * 2 + half] = pk.u4;
}

// ---------------------------------------------------------------------------
// Kernel 2: sim with native half2 HFMA2 dot partials (no per-element
// converts: was ~32 F2F/iter, now 4). v kept as half2 registers.
// ---------------------------------------------------------------------------
__global__ void sim_kernel(const int* __restrict__ members,
                           const int* __restrict__ eids) {
    int warp = (blockIdx.x * blockDim.x + threadIdx.x) >> 5;
    int lane = threadIdx.x & 31;
    int m0 = warp * 32;
    if (m0 >= MEDGE) return;

    int my_b = ((lane & 1) << 4) | (lane >> 1);

    int my_node = members[m0 + lane];
    int my_e    = eids[m0 + lane];

    union { uint4 u; __half2 h[4]; } v0, v1;   // center slices (half2)
    int   cur_e = -1;
    float acc   = 0.f;

    for (int i = 0; i < 32; i++) {
        int node = __shfl_sync(0xffffffffu, my_node, i);
        int e    = __shfl_sync(0xffffffffu, my_e, i);

        if (e != cur_e) {
            if (cur_e >= 0)
                atomicAdd(&g_acc[(size_t)my_b * EEDGE + cur_e], acc);
            acc = 0.f;
            const uint4* pv = g_fhat + (size_t)e * 64;
            v0.u = pv[lane];
            v1.u = pv[32 + lane];
            cur_e = e;
        }

        const uint4* pu = g_fhat + (size_t)node * 64;
        union { uint4 u; __half2 h[4]; } b0, b1;
        b0.u = pu[lane];
        b1.u = pu[32 + lane];

        // half2 dot partials: 4 HFMA2 per q, then one convert + fold
        __half2 a0 = __hmul2(b0.h[0], v0.h[0]);
        a0 = __hfma2(b0.h[1], v0.h[1], a0);
        a0 = __hfma2(b0.h[2], v0.h[2], a0);
        a0 = __hfma2(b0.h[3], v0.h[3], a0);
        __half2 a1 = __hmul2(b1.h[0], v1.h[0]);
        a1 = __hfma2(b1.h[1], v1.h[1], a1);
        a1 = __hfma2(b1.h[2], v1.h[2], a1);
        a1 = __hfma2(b1.h[3], v1.h[3], a1);

        float2 f0 = __half22float2(a0);
        float2 f1 = __half22float2(a1);
        float d0 = f0.x + f0.y;
        float d1 = f1.x + f1.y;

        // complete dots across channel-half pairs
        d0 += __shfl_xor_sync(0xffffffffu, d0, 1);
        d1 += __shfl_xor_sync(0xffffffffu, d1, 1);

        float d = (lane & 1) ? d1 : d0;   // owned q == lane&1
        acc += fminf(fmaxf(d, 0.f), 1.f);
    }
    atomicAdd(&g_acc[(size_t)my_b * EEDGE + cur_e], acc);
}

// ---------------------------------------------------------------------------
// Kernel 3: fused finalize (unchanged). Grid (NCHUNK, BB), block 256.
// ---------------------------------------------------------------------------
__global__ void finalize_kernel(const float* __restrict__ W,
                                float* __restrict__ out) {
    int b = blockIdx.y;
    const float4* arow = reinterpret_cast<const float4*>(g_acc + (size_t)b * EEDGE);
    const float4* crow = reinterpret_cast<const float4*>(g_icnt);
    const int NV4 = EEDGE / 4;                        // 1250

    float mn = 1e30f, mx = 0.f;                       // values >= 0
#pragma unroll
    for (int k = 0; k < NCHUNK; k++) {
        int i4 = k * 256 + threadIdx.x;
        if (i4 < NV4) {
            float4 a = arow[i4];
            float4 c = crow[i4];
            float s0 = a.x * c.x, s1 = a.y * c.y, s2 = a.z * c.z, s3 = a.w * c.w;
            mn = fminf(mn, fminf(fminf(s0, s1), fminf(s2, s3)));
            mx = fmaxf(mx, fmaxf(fmaxf(s0, s1), fmaxf(s2, s3)));
        }
    }
#pragma unroll
    for (int o = 16; o; o >>= 1) {
        mn = fminf(mn, __shfl_xor_sync(0xffffffffu, mn, o));
        mx = fmaxf(mx, __shfl_xor_sync(0xffffffffu, mx, o));
    }
    __shared__ float smn[8], smx[8];
    int wid = threadIdx.x >> 5, lane = threadIdx.x & 31;
    if (lane == 0) { smn[wid] = mn; smx[wid] = mx; }
    __syncthreads();
    mn = smn[0]; mx = smx[0];
#pragma unroll
    for (int i = 1; i < 8; i++) {
        mn = fminf(mn, smn[i]);
        mx = fmaxf(mx, smx[i]);
    }
    float inv = LAMW / (mx - mn + EPSW);

    int i4 = blockIdx.x * 256 + threadIdx.x;
    if (i4 < NV4) {
        float4 a = arow[i4];
        float4 c = crow[i4];
        float4 w = reinterpret_cast<const float4*>(W)[i4];
        float4 o;
        o.x = w.x * (1.f + (a.x * c.x - mn) * inv);
        o.y = w.y * (1.f + (a.y * c.y - mn) * inv);
        o.z = w.z * (1.f + (a.z * c.z - mn) * inv);
        o.w = w.w * (1.f + (a.w * c.w - mn) * inv);
        reinterpret_cast<float4*>(out + (size_t)b * EEDGE)[i4] = o;
    }
}

// ---------------------------------------------------------------------------
extern "C" void kernel_launch(void* const* d_in, const int* in_sizes, int n_in,
                              void* d_out, int out_size) {
    const float* x_raw   = (const float*)d_in[0];
    const float* W       = (const float*)d_in[1];
    const int*   members = (const int*)d_in[2];
    // d_in[3] = centers (== arange(E), unused)
    const int*   eids    = (const int*)d_in[4];
    const float* counts  = (const float*)d_in[5];
    float*       out     = (float*)d_out;

    feat_kernel<<<(2 * BB * NNODE + 255) / 256, 256>>>(x_raw, counts);

    int warps  = (MEDGE + 31) / 32;                 // 5000
    int blocks = (warps * 32 + 255) / 256;          // 625
    sim_kernel<<<blocks, 256>>>(members, eids);

    dim3 fin_grid(NCHUNK, BB);
    finalize_kernel<<<fin_grid, 256>>>(W, out);
}